// round 2
// baseline (speedup 1.0000x reference)
#include <cuda_runtime.h>
#include <math.h>

// Problem constants
#define N_RES    2048
#define D_IN     128
#define T_SEQ    2048
#define GRID     128      // CTAs; 16 rows each; all wave-1 resident (<=152 SMs)
#define ROWS     16       // reservoir rows per CTA
#define NTHREADS 256      // 8 warps, 2 rows per warp

__device__ unsigned g_esn_ctr;   // grid-barrier counter (monotonic within launch)

__global__ void esn_zero_kernel() { g_esn_ctr = 0u; }

__device__ __forceinline__ unsigned ld_acquire_gpu(const unsigned* p) {
    unsigned v;
    asm volatile("ld.acquire.gpu.global.u32 %0, [%1];" : "=r"(v) : "l"(p) : "memory");
    return v;
}
__device__ __forceinline__ void red_release_add1(unsigned* p) {
    asm volatile("red.release.gpu.global.add.u32 [%0], 1;" :: "l"(p) : "memory");
}

extern __shared__ float smem_esn[];  // [ROWS*N_RES] W_res slice + [ROWS*D_IN] W_in slice

__global__ void __launch_bounds__(NTHREADS, 1)
esn_kernel(const float* __restrict__ inp,    // (T, D_IN)
           const float* __restrict__ Win,    // (N_RES, D_IN)
           const float* __restrict__ Wres,   // (N_RES, N_RES)
           float*       __restrict__ out)    // (T, N_RES) -- rows double as state x_t
{
    float* sW   = smem_esn;                  // ROWS x N_RES  (fp32)
    float* sWin = smem_esn + ROWS * N_RES;   // ROWS x D_IN   (fp32)

    const int tid  = threadIdx.x;
    const int row0 = blockIdx.x * ROWS;

    // ---- stage this CTA's weight slices into SMEM (once) ----
    {
        const float4* g = (const float4*)(Wres + (size_t)row0 * N_RES);
        float4*       s = (float4*)sW;
        for (int i = tid; i < ROWS * N_RES / 4; i += NTHREADS) s[i] = g[i];
        const float4* gi = (const float4*)(Win + (size_t)row0 * D_IN);
        float4*       si = (float4*)sWin;
        for (int i = tid; i < ROWS * D_IN / 4; i += NTHREADS) si[i] = gi[i];
    }
    __syncthreads();

    const int warp = tid >> 5;
    const int lane = tid & 31;
    const float inv_sqrt_n = 0.022097086912079612f;  // 1/sqrt(2048)

    for (int t = 0; t < T_SEQ; ++t) {
        // ---- wait for step t-1 to be fully published (grid barrier) ----
        if (t > 0) {
            if (tid == 0) {
                const unsigned target = (unsigned)GRID * (unsigned)t;
                while (ld_acquire_gpu(&g_esn_ctr) < target) { }
            }
            __syncthreads();   // chains tid0's acquire to all threads' loads
        }

        // ---- load x_{t-1} (full 2048 floats) into registers, L2 path ----
        float4 xv[16];
        if (t > 0) {
            const float4* xr = (const float4*)(out + (size_t)(t - 1) * N_RES);
            #pragma unroll
            for (int k = 0; k < 16; ++k) xv[k] = __ldcg(xr + lane + 32 * k);
        }
        // input row for step t (128 floats; one float4 per lane)
        const float4 iv = __ldg((const float4*)(inp + (size_t)t * D_IN) + lane);

        // ---- 2 reservoir rows per warp ----
        #pragma unroll
        for (int r = 0; r < 2; ++r) {
            const int row = warp * 2 + r;  // local row in [0, ROWS)

            // u_t[row] contribution: W_in[row] . inp[t]
            const float4 w = ((const float4*)(sWin + row * D_IN))[lane];
            float acc = w.x * iv.x + w.y * iv.y + w.z * iv.z + w.w * iv.w;

            // W_res[row] . x_{t-1}
            if (t > 0) {
                const float4* wr = (const float4*)(sW + row * N_RES);
                #pragma unroll
                for (int k = 0; k < 16; ++k) {
                    const float4 ww = wr[lane + 32 * k];
                    acc += ww.x * xv[k].x;
                    acc += ww.y * xv[k].y;
                    acc += ww.z * xv[k].z;
                    acc += ww.w * xv[k].w;
                }
            }

            // butterfly reduce across the warp
            #pragma unroll
            for (int off = 16; off; off >>= 1)
                acc += __shfl_xor_sync(0xffffffffu, acc, off);

            if (lane == 0)
                out[(size_t)t * N_RES + row0 + row] = erff(acc) * inv_sqrt_n;
        }

        // ---- publish step t: all writes done -> release-arrive ----
        __syncthreads();
        if (tid == 0) red_release_add1(&g_esn_ctr);
    }
}

extern "C" void kernel_launch(void* const* d_in, const int* in_sizes, int n_in,
                              void* d_out, int out_size) {
    const float* inp  = (const float*)d_in[0];   // input_data (2048,128)
    const float* Win  = (const float*)d_in[1];   // W_in       (2048,128)
    const float* Wres = (const float*)d_in[2];   // W_res      (2048,2048)
    float* out = (float*)d_out;                  // (2048,2048) float32

    const size_t smem = (size_t)(ROWS * N_RES + ROWS * D_IN) * sizeof(float); // 139264 B
    cudaFuncSetAttribute(esn_kernel,
                         cudaFuncAttributeMaxDynamicSharedMemorySize, (int)smem);

    esn_zero_kernel<<<1, 1>>>();
    esn_kernel<<<GRID, NTHREADS, smem>>>(inp, Win, Wres, out);
}

// round 4
// speedup vs baseline: 1.1337x; 1.1337x over previous
#include <cuda_runtime.h>
#include <math.h>

// Problem constants
#define N_RES 2048
#define D_IN  128
#define T_SEQ 2048
#define GRID  128      // CTAs, all wave-1 resident (<=152 SMs) -- required for grid barrier
#define ROWS  16       // reservoir rows per CTA
#define NTH   256      // 8 warps; each warp owns a 256-column chunk

// Scratch (allocation-free rule: __device__ globals)
__device__ float    g_U[(size_t)T_SEQ * N_RES];  // 16 MB: U = input @ W_in^T
__device__ unsigned g_flags[GRID * 8];           // per-CTA step counters, 32B stride

__global__ void esn_zero_kernel() {
    int i = threadIdx.x;
    if (i < GRID) g_flags[i * 8] = 0u;
}

__device__ __forceinline__ unsigned ld_acq(const unsigned* p) {
    unsigned v;
    asm volatile("ld.acquire.gpu.global.u32 %0, [%1];" : "=r"(v) : "l"(p) : "memory");
    return v;
}
__device__ __forceinline__ void st_rel(unsigned* p, unsigned v) {
    asm volatile("st.release.gpu.global.u32 [%0], %1;" :: "l"(p), "r"(v) : "memory");
}
// Packed fp32x2 FMA (Blackwell; ptxas never auto-fuses this from C++)
__device__ __forceinline__ unsigned long long ffma2(unsigned long long a,
                                                    unsigned long long b,
                                                    unsigned long long c) {
    unsigned long long d;
    asm("fma.rn.f32x2 %0, %1, %2, %3;" : "=l"(d) : "l"(a), "l"(b), "l"(c));
    return d;
}
__device__ __forceinline__ float hadd2(unsigned long long a) {
    unsigned lo, hi;
    asm("mov.b64 {%0,%1}, %2;" : "=r"(lo), "=r"(hi) : "l"(a));
    return __uint_as_float(lo) + __uint_as_float(hi);
}
// L2-path (L1-bypassing) 16B load of two packed f32x2
__device__ __forceinline__ void ldcg_v2u64(const void* p,
                                           unsigned long long& a, unsigned long long& b) {
    asm volatile("ld.global.cg.v2.u64 {%0,%1}, [%2];" : "=l"(a), "=l"(b) : "l"(p));
}

__global__ void __launch_bounds__(NTH, 1)
esn_kernel(const float* __restrict__ inp,    // (T, D_IN)
           const float* __restrict__ Win,    // (N_RES, D_IN)
           const float* __restrict__ Wres,   // (N_RES, N_RES)
           float*       __restrict__ out)    // (T, N_RES): row t is state x_t
{
    __shared__ float sWin[ROWS * D_IN];      // 8 KB
    __shared__ float sPart[ROWS * 8];        // [row][warp] partial sums

    const int tid  = threadIdx.x;
    const int bid  = blockIdx.x;
    const int row0 = bid * ROWS;
    const int warp = tid >> 5;
    const int lane = tid & 31;
    const int cb   = warp * 256 + lane * 8;  // this thread's 8-column base

    // ---- stage W_in slice into SMEM ----
    for (int i = tid; i < ROWS * D_IN; i += NTH)
        sWin[i] = Win[(size_t)row0 * D_IN + i];
    __syncthreads();

    // ---- prologue: U[t][row0..row0+15] for all t (no cross-CTA dependency) ----
    for (int it = 0; it < T_SEQ / NTH; ++it) {
        const int t = it * NTH + tid;
        float4 xin[D_IN / 4];
        const float4* ip = (const float4*)(inp + (size_t)t * D_IN);
        #pragma unroll
        for (int k = 0; k < D_IN / 4; ++k) xin[k] = ip[k];
        #pragma unroll
        for (int r = 0; r < ROWS; ++r) {
            const float4* wr = (const float4*)(sWin + r * D_IN);  // broadcast LDS
            float acc = 0.f;
            #pragma unroll
            for (int k = 0; k < D_IN / 4; ++k) {
                float4 w = wr[k];
                acc += w.x * xin[k].x + w.y * xin[k].y + w.z * xin[k].z + w.w * xin[k].w;
            }
            g_U[(size_t)t * N_RES + row0 + r] = acc;
        }
    }

    // ---- W_res slice into REGISTERS: 16 rows x 8 cols = 128 regs (packed f32x2) ----
    unsigned long long wv[ROWS][4];
    #pragma unroll
    for (int r = 0; r < ROWS; ++r) {
        const ulonglong2* p = (const ulonglong2*)(Wres + (size_t)(row0 + r) * N_RES + cb);
        ulonglong2 q0 = p[0], q1 = p[1];
        wv[r][0] = q0.x; wv[r][1] = q0.y; wv[r][2] = q1.x; wv[r][3] = q1.y;
    }
    __syncthreads();   // g_U visible CTA-wide before the recurrence reads it

    const bool  fin  = ((tid & 15) == 0);     // 16 finisher threads (one per row)
    const int   frow = tid >> 4;
    const float c    = 0.022097086912079612f; // 1/sqrt(2048)

    for (int t = 0; t < T_SEQ; ++t) {
        // ---- wait: every CTA has published step t-1 ----
        if (t > 0 && tid < GRID) {
            const unsigned* fp = &g_flags[tid * 8];
            while (ld_acq(fp) < (unsigned)t) { }
        }
        __syncthreads();                                   // (a)

        float uval = 0.f;
        if (fin) uval = g_U[(size_t)t * N_RES + row0 + frow];  // prefetch early

        if (t > 0) {
            // x chunk: this thread's 8 values of x_{t-1} (L2 path)
            unsigned long long x0, x1, x2, x3;
            const char* xp = (const char*)(out + (size_t)(t - 1) * N_RES + cb);
            ldcg_v2u64(xp,      x0, x1);
            ldcg_v2u64(xp + 16, x2, x3);

            // 16 rows x 4 packed FMAs, butterfly-reduce each row across the warp
            #pragma unroll
            for (int r = 0; r < ROWS; ++r) {
                unsigned long long a = ffma2(wv[r][0], x0, 0ull);
                a = ffma2(wv[r][1], x1, a);
                a = ffma2(wv[r][2], x2, a);
                a = ffma2(wv[r][3], x3, a);
                float s = hadd2(a);
                s += __shfl_xor_sync(0xffffffffu, s, 1);
                s += __shfl_xor_sync(0xffffffffu, s, 2);
                s += __shfl_xor_sync(0xffffffffu, s, 4);
                s += __shfl_xor_sync(0xffffffffu, s, 8);
                s += __shfl_xor_sync(0xffffffffu, s, 16);
                if (lane == r) sPart[r * 8 + warp] = s;    // predicated, unrolled
            }
        }
        __syncthreads();                                   // (b)

        if (fin) {
            float pre = uval;
            if (t > 0) {
                const float4* pp = (const float4*)(sPart + frow * 8);
                float4 p0 = pp[0], p1 = pp[1];
                pre += p0.x + p0.y + p0.z + p0.w + p1.x + p1.y + p1.z + p1.w;
            }
            out[(size_t)t * N_RES + row0 + frow] = erff(pre) * c;
        }
        __syncthreads();                                   // (c)

        if (tid == 0) st_rel(&g_flags[bid * 8], (unsigned)(t + 1));
    }
}

extern "C" void kernel_launch(void* const* d_in, const int* in_sizes, int n_in,
                              void* d_out, int out_size) {
    const float* inp  = (const float*)d_in[0];   // input_data (2048,128)
    const float* Win  = (const float*)d_in[1];   // W_in       (2048,128)
    const float* Wres = (const float*)d_in[2];   // W_res      (2048,2048)
    float* out = (float*)d_out;                  // (2048,2048) float32

    esn_zero_kernel<<<1, 128>>>();
    esn_kernel<<<GRID, NTH>>>(inp, Win, Wres, out);
}